// round 4
// baseline (speedup 1.0000x reference)
#include <cuda_runtime.h>

#define BS 8192
#define C 23
#define F 1024
#define CF (C * F)         /* 23552 */
#define CF4 (CF / 4)       /* 5888  */
#define NCHUNK 16
#define ROWS (BS / NCHUNK) /* 512 */
#define NBT (BS / 32)      /* 256 batch tiles per channel in k3 */
#define EPS 1e-5f

// Scratch (__device__ globals; no allocations allowed)
__device__ float g_partial[(size_t)NCHUNK * 2 * CF]; // [chunk][{sum,sumsq}][CF]  ~3 MB
__device__ float g_s[CF];          // fused per-(c,f) scale: rsqrt(var1+eps)*gamma1*W1
__device__ float g_h[C * BS];      // h TRANSPOSED: [c][b]
__device__ float2 g_p2[C * NBT];   // per-(channel, batch-tile) (sum h, sum h^2)

// ---------------------------------------------------------------------------
// k1: per-(c,f) partial sums of x and x^2 over a 512-row batch chunk.
// grid (23, 16), block 256 — all 368 blocks chip-resident.
// ---------------------------------------------------------------------------
__global__ void k1_colsums(const float* __restrict__ x) {
    int cf4 = blockIdx.x * 256 + threadIdx.x;   // 0..5887
    int chunk = blockIdx.y;                     // 0..15
    const float4* xp = (const float4*)x;
    long base = (long)chunk * ROWS * CF4 + cf4;

    float4 s = make_float4(0.f, 0.f, 0.f, 0.f);
    float4 q = make_float4(0.f, 0.f, 0.f, 0.f);
#pragma unroll 8
    for (int r = 0; r < ROWS; r++) {
        float4 v = __ldcs(&xp[base + (long)r * CF4]);   // streaming: no reuse
        s.x += v.x; s.y += v.y; s.z += v.z; s.w += v.w;
        q.x += v.x * v.x; q.y += v.y * v.y; q.z += v.z * v.z; q.w += v.w * v.w;
    }
    ((float4*)g_partial)[(long)chunk * 2 * CF4 + cf4] = s;
    ((float4*)g_partial)[(long)chunk * 2 * CF4 + CF4 + cf4] = q;
}

// ---------------------------------------------------------------------------
// k2: fold NCHUNK partials -> s[c,f] = rsqrt(var1+eps) * gamma1 * W1
// grid 92, block 256 (one thread per (c,f)). Partials are L2-resident.
// ---------------------------------------------------------------------------
__global__ void k2_scale(const float* __restrict__ gamma1,
                         const float* __restrict__ W1) {
    int cf = blockIdx.x * 256 + threadIdx.x;
    float s = 0.f, q = 0.f;
#pragma unroll
    for (int k = 0; k < NCHUNK; k++) {
        s += g_partial[(long)k * 2 * CF + cf];
        q += g_partial[(long)k * 2 * CF + CF + cf];
    }
    float mean = s * (1.0f / BS);
    float var  = q * (1.0f / BS) - mean * mean;
    g_s[cf] = rsqrtf(var + EPS) * gamma1[cf] * W1[cf];
}

// ---------------------------------------------------------------------------
// k3: h[c][b] = dot(x[b,c,:], s[c,:]) + per-block (sum h, sum h^2) partial.
// Block = one channel c + 32 batch rows; s[c] staged in shared; warp = 4 rows.
// grid 23*256 = 5888, block 256.
// ---------------------------------------------------------------------------
__global__ void k3_dot(const float* __restrict__ x) {
    __shared__ float4 ss[256];
    __shared__ float2 sh_p[8];
    int c = blockIdx.x % C;
    int btile = blockIdx.x / C;                 // 0..255
    ss[threadIdx.x] = ((const float4*)g_s)[c * 256 + threadIdx.x];
    __syncthreads();

    int w = threadIdx.x >> 5, lane = threadIdx.x & 31;
    int b0 = btile * 32 + w * 4;

    float acc[4];
#pragma unroll
    for (int j = 0; j < 4; j++) {
        const float4* xp = (const float4*)x + ((long)(b0 + j) * C + c) * 256;
        float a = 0.f;
#pragma unroll
        for (int i = 0; i < 8; i++) {
            float4 v  = __ldcs(&xp[lane + 32 * i]);   // streaming: no reuse
            float4 wv = ss[lane + 32 * i];
            a += v.x * wv.x; a += v.y * wv.y;
            a += v.z * wv.z; a += v.w * wv.w;
        }
        acc[j] = a;
    }
#pragma unroll
    for (int o = 16; o; o >>= 1) {
#pragma unroll
        for (int j = 0; j < 4; j++)
            acc[j] += __shfl_xor_sync(0xffffffffu, acc[j], o);
    }
    if (lane == 0) {
        // transposed store: h[c][b0..b0+3] -> one STG.128
        *(float4*)(&g_h[c * BS + b0]) =
            make_float4(acc[0], acc[1], acc[2], acc[3]);
        // warp-local stats partial (fixed order -> deterministic)
        float ps = acc[0] + acc[1] + acc[2] + acc[3];
        float pq = acc[0] * acc[0] + acc[1] * acc[1]
                 + acc[2] * acc[2] + acc[3] * acc[3];
        sh_p[w] = make_float2(ps, pq);
    }
    __syncthreads();
    if (threadIdx.x == 0) {
        float s = 0.f, q = 0.f;
#pragma unroll
        for (int i = 0; i < 8; i++) { s += sh_p[i].x; q += sh_p[i].y; }
        g_p2[c * NBT + btile] = make_float2(s, q);
    }
}

// ---------------------------------------------------------------------------
// k45: fused BatchNorm1d(23) stats + final Linear(23,1).
// grid 32, block 256. Each block redundantly folds the 47 KB partial buffer
// (L2-resident) into per-channel (mean2, k2) in shared — warp w owns channels
// {3w, 3w+1, 3w+2} — then computes its 256-row slice of out.
// ---------------------------------------------------------------------------
__global__ void k45_out(const float* __restrict__ gamma2,
                        const float* __restrict__ beta2,
                        const float* __restrict__ W2,
                        const float* __restrict__ b2,
                        float* __restrict__ out) {
    __shared__ float s_mean[C + 1], s_k2[C + 1];
    int lane = threadIdx.x & 31, w = threadIdx.x >> 5;

    // per-channel stats: warp w handles channels 3w..3w+2 (8 warps cover 24>=23)
#pragma unroll
    for (int j = 0; j < 3; j++) {
        int c = w * 3 + j;
        if (c < C) {
            float s = 0.f, q = 0.f;
#pragma unroll
            for (int i = 0; i < 8; i++) {
                float2 p = g_p2[c * NBT + lane + 32 * i];
                s += p.x; q += p.y;
            }
#pragma unroll
            for (int o = 16; o; o >>= 1) {
                s += __shfl_xor_sync(0xffffffffu, s, o);
                q += __shfl_xor_sync(0xffffffffu, q, o);
            }
            if (lane == 0) {
                float mean = s * (1.0f / BS);
                float var  = q * (1.0f / BS) - mean * mean;
                s_mean[c] = mean;
                s_k2[c]   = rsqrtf(var + EPS) * gamma2[c] * W2[c];
            }
        }
    }
    __syncthreads();

    int b = blockIdx.x * 256 + threadIdx.x;
    float off = b2[0];
#pragma unroll
    for (int c = 0; c < C; c++) off += beta2[c] * W2[c];
    float a = 0.f;
#pragma unroll
    for (int c = 0; c < C; c++)
        a += (g_h[c * BS + b] - s_mean[c]) * s_k2[c];
    out[b] = a + off;
}

extern "C" void kernel_launch(void* const* d_in, const int* in_sizes, int n_in,
                              void* d_out, int out_size) {
    const float* x      = (const float*)d_in[0];
    const float* gamma1 = (const float*)d_in[1];
    /* beta1 = d_in[2], b1 = d_in[4]: algebraically cancelled by BatchNorm1d(23) */
    const float* W1     = (const float*)d_in[3];
    const float* gamma2 = (const float*)d_in[5];
    const float* beta2  = (const float*)d_in[6];
    const float* W2     = (const float*)d_in[7];
    const float* b2     = (const float*)d_in[8];
    float* out = (float*)d_out;

    k1_colsums<<<dim3(23, NCHUNK), 256>>>(x);
    k2_scale<<<CF / 256, 256>>>(gamma1, W1);
    k3_dot<<<C * (BS / 32), 256>>>(x);
    k45_out<<<BS / 256, 256>>>(gamma2, beta2, W2, b2, out);
}

// round 5
// speedup vs baseline: 1.0521x; 1.0521x over previous
#include <cuda_runtime.h>

#define BS 8192
#define C 23
#define F 1024
#define CF (C * F)         /* 23552 */
#define CF4 (CF / 4)       /* 5888  */
#define NCHUNK 16
#define ROWS (BS / NCHUNK) /* 512 rows per chunk */
#define TPC 16             /* 32-row tiles per chunk (512/32) */
#define EPS 1e-5f

// Scratch (__device__ globals; no allocations allowed)
__device__ float g_partial[(size_t)NCHUNK * 2 * CF]; // [chunk][{sum,sumsq}][CF] ~3 MB
__device__ float g_s[CF];        // fused per-(c,f) scale: rsqrt(var1+eps)*gamma1*W1
__device__ float g_h[C * BS];    // h TRANSPOSED: [c][b]
__device__ float g_mean2[C];
__device__ float g_k2[C];        // rsqrt(var2+eps)*gamma2*W2

// ---------------------------------------------------------------------------
// k1: per-(c,f) partial sums of x and x^2 over a 512-row batch chunk.
// grid (23, 16), block 256 — all 368 blocks chip-resident, finish together.
// Default (evict-normal) loads: the tail of each chunk's stream stays in L2
// for k3 to harvest.
// ---------------------------------------------------------------------------
__global__ void k1_colsums(const float* __restrict__ x) {
    int cf4 = blockIdx.x * 256 + threadIdx.x;   // 0..5887
    int chunk = blockIdx.y;                     // 0..15
    const float4* xp = (const float4*)x;
    long base = (long)chunk * ROWS * CF4 + cf4;

    float4 s = make_float4(0.f, 0.f, 0.f, 0.f);
    float4 q = make_float4(0.f, 0.f, 0.f, 0.f);
#pragma unroll 8
    for (int r = 0; r < ROWS; r++) {
        float4 v = __ldg(&xp[base + (long)r * CF4]);
        s.x += v.x; s.y += v.y; s.z += v.z; s.w += v.w;
        q.x += v.x * v.x; q.y += v.y * v.y; q.z += v.z * v.z; q.w += v.w * v.w;
    }
    ((float4*)g_partial)[(long)chunk * 2 * CF4 + cf4] = s;
    ((float4*)g_partial)[(long)chunk * 2 * CF4 + CF4 + cf4] = q;
}

// ---------------------------------------------------------------------------
// k2: fold NCHUNK partials -> s[c,f] = rsqrt(var1+eps) * gamma1 * W1
// grid 92, block 256 (one thread per (c,f)). Partials are L2-resident.
// ---------------------------------------------------------------------------
__global__ void k2_scale(const float* __restrict__ gamma1,
                         const float* __restrict__ W1) {
    int cf = blockIdx.x * 256 + threadIdx.x;
    float s = 0.f, q = 0.f;
#pragma unroll
    for (int k = 0; k < NCHUNK; k++) {
        s += g_partial[(long)k * 2 * CF + cf];
        q += g_partial[(long)k * 2 * CF + CF + cf];
    }
    float mean = s * (1.0f / BS);
    float var  = q * (1.0f / BS) - mean * mean;
    g_s[cf] = rsqrtf(var + EPS) * gamma1[cf] * W1[cf];
}

// ---------------------------------------------------------------------------
// k3: h[c][b] = dot(x[b,c,:], s[c,:]).  Block = one channel c + 32 batch rows.
// Batch-tile schedule REORDERED to harvest k1's L2 residue: early blocks take
// the tail tiles of every chunk (the most recently streamed rows), walking
// backward toward the cold head rows.
// grid 23*256 = 5888, block 256.
// ---------------------------------------------------------------------------
__global__ void k3_dot(const float* __restrict__ x) {
    __shared__ float4 ss[256];
    int c = blockIdx.x % C;
    int l = blockIdx.x / C;                     // launch-order tile index 0..255
    // remap: visit per-chunk tail tiles first, uniformly across chunks
    int rank  = l >> 4;                         // 0..15 (0 = hottest)
    int chunk = l & 15;                         // 0..15
    int btile = chunk * TPC + (TPC - 1 - rank); // actual 32-row tile
    ss[threadIdx.x] = ((const float4*)g_s)[c * 256 + threadIdx.x];
    __syncthreads();

    int w = threadIdx.x >> 5, lane = threadIdx.x & 31;
    int b0 = btile * 32 + w * 4;

    float acc[4];
#pragma unroll
    for (int j = 0; j < 4; j++) {
        const float4* xp = (const float4*)x + ((long)(b0 + j) * C + c) * 256;
        float a = 0.f;
#pragma unroll
        for (int i = 0; i < 8; i++) {
            float4 v  = __ldcs(&xp[lane + 32 * i]);   // no further reuse
            float4 wv = ss[lane + 32 * i];
            a += v.x * wv.x; a += v.y * wv.y;
            a += v.z * wv.z; a += v.w * wv.w;
        }
        acc[j] = a;
    }
#pragma unroll
    for (int o = 16; o; o >>= 1) {
#pragma unroll
        for (int j = 0; j < 4; j++)
            acc[j] += __shfl_xor_sync(0xffffffffu, acc[j], o);
    }
    if (lane == 0) {
        // transposed store: h[c][b0..b0+3] -> one STG.128
        *(float4*)(&g_h[c * BS + b0]) =
            make_float4(acc[0], acc[1], acc[2], acc[3]);
    }
}

// ---------------------------------------------------------------------------
// k4: BatchNorm1d(23) batch stats over h[c][:] (contiguous, coalesced).
// grid 23, block 1024.
// ---------------------------------------------------------------------------
__global__ void k4_stats(const float* __restrict__ gamma2,
                         const float* __restrict__ W2) {
    __shared__ float sh_s[32], sh_q[32];
    int c = blockIdx.x;
    int t = threadIdx.x, lane = t & 31, w = t >> 5;

    const float4* hp = (const float4*)(&g_h[c * BS]);
    float s = 0.f, q = 0.f;
#pragma unroll
    for (int i = 0; i < 2; i++) {
        float4 v = hp[t + 1024 * i];
        s += v.x + v.y + v.z + v.w;
        q += v.x * v.x + v.y * v.y + v.z * v.z + v.w * v.w;
    }
#pragma unroll
    for (int o = 16; o; o >>= 1) {
        s += __shfl_xor_sync(0xffffffffu, s, o);
        q += __shfl_xor_sync(0xffffffffu, q, o);
    }
    if (lane == 0) { sh_s[w] = s; sh_q[w] = q; }
    __syncthreads();
    if (w == 0) {
        s = sh_s[lane]; q = sh_q[lane];
#pragma unroll
        for (int o = 16; o; o >>= 1) {
            s += __shfl_xor_sync(0xffffffffu, s, o);
            q += __shfl_xor_sync(0xffffffffu, q, o);
        }
        if (lane == 0) {
            float mean = s * (1.0f / BS);
            float var  = q * (1.0f / BS) - mean * mean;
            g_mean2[c] = mean;
            g_k2[c]    = rsqrtf(var + EPS) * gamma2[c] * W2[c];
        }
    }
}

// ---------------------------------------------------------------------------
// k5: out[b] = sum_c (h[c][b]-mean2[c])*k2[c] + (sum_c beta2*W2 + b2)
// grid 32, block 256. h[c][b] reads coalesced; h is L2-resident.
// ---------------------------------------------------------------------------
__global__ void k5_out(const float* __restrict__ beta2,
                       const float* __restrict__ W2,
                       const float* __restrict__ b2,
                       float* __restrict__ out) {
    int b = blockIdx.x * 256 + threadIdx.x;
    float off = b2[0];
#pragma unroll
    for (int c = 0; c < C; c++) off += beta2[c] * W2[c];
    float a = 0.f;
#pragma unroll
    for (int c = 0; c < C; c++)
        a += (g_h[c * BS + b] - g_mean2[c]) * g_k2[c];
    out[b] = a + off;
}

extern "C" void kernel_launch(void* const* d_in, const int* in_sizes, int n_in,
                              void* d_out, int out_size) {
    const float* x      = (const float*)d_in[0];
    const float* gamma1 = (const float*)d_in[1];
    /* beta1 = d_in[2], b1 = d_in[4]: algebraically cancelled by BatchNorm1d(23) */
    const float* W1     = (const float*)d_in[3];
    const float* gamma2 = (const float*)d_in[5];
    const float* beta2  = (const float*)d_in[6];
    const float* W2     = (const float*)d_in[7];
    const float* b2     = (const float*)d_in[8];
    float* out = (float*)d_out;

    k1_colsums<<<dim3(23, NCHUNK), 256>>>(x);
    k2_scale<<<CF / 256, 256>>>(gamma1, W1);
    k3_dot<<<C * (BS / 32), 256>>>(x);
    k4_stats<<<C, 1024>>>(gamma2, W2);
    k5_out<<<BS / 256, 256>>>(beta2, W2, b2, out);
}